// round 1
// baseline (speedup 1.0000x reference)
#include <cuda_runtime.h>
#include <math.h>

#define Bb 4
#define Ss 1024
#define Dd 1024
#define Hh 16
#define HD 64
#define BHt (Bb*Hh)
#define Mrows (Bb*Ss)

// ---------------- device scratch (no allocations allowed) ----------------
__device__ float g_q[(size_t)Bb*Ss*Dd];
__device__ float g_k[(size_t)Bb*Ss*Dd];
__device__ float g_v[(size_t)Bb*Ss*Dd];
__device__ float g_x[(size_t)Bb*Ss*Dd];
__device__ float g_rowsum[(size_t)BHt*Ss];
__device__ float g_p_fallback[(size_t)BHt*Ss*Ss];  // used only if out_size lacks attention

// ---------------- 128x128x8 fp32 GEMM + bias: C = A*W + b ----------------
__global__ __launch_bounds__(256) void sgemm_bias(
    const float* __restrict__ A, const float* __restrict__ W,
    const float* __restrict__ bias, float* __restrict__ C,
    int Mn, int Nn, int Kn)
{
    __shared__ float As[8][128];
    __shared__ float Ws[8][128];
    const int tid = threadIdx.x;
    const int bm = blockIdx.y * 128;
    const int bn = blockIdx.x * 128;
    const int aRow = tid >> 1, aCol = (tid & 1) << 2;   // 128 rows x 8 cols
    const int wRow = tid >> 5, wCol = (tid & 31) << 2;  // 8 rows x 128 cols
    const int ty = tid >> 4, tx = tid & 15;

    float acc[8][8];
#pragma unroll
    for (int i = 0; i < 8; i++)
#pragma unroll
        for (int j = 0; j < 8; j++) acc[i][j] = 0.f;

    for (int k0 = 0; k0 < Kn; k0 += 8) {
        float4 av = *(const float4*)(A + (size_t)(bm + aRow) * Kn + k0 + aCol);
        As[aCol + 0][aRow] = av.x;
        As[aCol + 1][aRow] = av.y;
        As[aCol + 2][aRow] = av.z;
        As[aCol + 3][aRow] = av.w;
        *(float4*)&Ws[wRow][wCol] =
            *(const float4*)(W + (size_t)(k0 + wRow) * Nn + bn + wCol);
        __syncthreads();
#pragma unroll
        for (int kk = 0; kk < 8; kk++) {
            float4 a0 = *(float4*)&As[kk][ty * 8];
            float4 a1 = *(float4*)&As[kk][ty * 8 + 4];
            float4 b0 = *(float4*)&Ws[kk][tx * 8];
            float4 b1 = *(float4*)&Ws[kk][tx * 8 + 4];
            float a[8] = {a0.x, a0.y, a0.z, a0.w, a1.x, a1.y, a1.z, a1.w};
            float b[8] = {b0.x, b0.y, b0.z, b0.w, b1.x, b1.y, b1.z, b1.w};
#pragma unroll
            for (int i = 0; i < 8; i++)
#pragma unroll
                for (int j = 0; j < 8; j++)
                    acc[i][j] = fmaf(a[i], b[j], acc[i][j]);
        }
        __syncthreads();
    }
#pragma unroll
    for (int i = 0; i < 8; i++) {
        size_t row = (size_t)bm + ty * 8 + i;
#pragma unroll
        for (int j = 0; j < 8; j += 4) {
            int col = bn + tx * 8 + j;
            float4 bv = *(const float4*)(bias + col);
            float4 o;
            o.x = acc[i][j + 0] + bv.x;
            o.y = acc[i][j + 1] + bv.y;
            o.z = acc[i][j + 2] + bv.z;
            o.w = acc[i][j + 3] + bv.w;
            *(float4*)(C + row * Nn + col) = o;
        }
    }
}

// ---------------- zero rowsums ----------------
__global__ void zero_rowsum()
{
    g_rowsum[(size_t)blockIdx.x * 1024 + threadIdx.x] = 0.f;
}

// ---- QK^T/sqrt(HD) + mask + exp, write unnormalized P, accumulate rowsums ----
__global__ __launch_bounds__(256) void attn_energy(
    const float* __restrict__ Q, const float* __restrict__ Kt,
    const int* __restrict__ mask, float* __restrict__ P)
{
    __shared__ float Qs[64][65];
    __shared__ float Ks[64][65];
    __shared__ float red[64][17];

    const int bh = blockIdx.z;
    const int b = bh >> 4, h = bh & 15;
    const int q0 = blockIdx.y << 6;
    const int k0 = blockIdx.x << 6;
    const int tid = threadIdx.x;

    const float* Qb = Q + ((size_t)b * Ss + q0) * Dd + h * HD;
    const float* Kb = Kt + ((size_t)b * Ss + k0) * Dd + h * HD;

#pragma unroll
    for (int i = 0; i < 4; i++) {
        int id = tid + i * 256;
        int row = id >> 4, col = (id & 15) << 2;
        float4 qv = *(const float4*)(Qb + (size_t)row * Dd + col);
        Qs[row][col + 0] = qv.x; Qs[row][col + 1] = qv.y;
        Qs[row][col + 2] = qv.z; Qs[row][col + 3] = qv.w;
        float4 kv = *(const float4*)(Kb + (size_t)row * Dd + col);
        Ks[row][col + 0] = kv.x; Ks[row][col + 1] = kv.y;
        Ks[row][col + 2] = kv.z; Ks[row][col + 3] = kv.w;
    }
    __syncthreads();

    const int ty = tid >> 4, tx = tid & 15;
    const int qb = ty << 2, kb = tx << 2;

    float acc[4][4];
#pragma unroll
    for (int i = 0; i < 4; i++)
#pragma unroll
        for (int j = 0; j < 4; j++) acc[i][j] = 0.f;

#pragma unroll 8
    for (int dd = 0; dd < 64; dd++) {
        float a[4], c[4];
#pragma unroll
        for (int i = 0; i < 4; i++) a[i] = Qs[qb + i][dd];
#pragma unroll
        for (int j = 0; j < 4; j++) c[j] = Ks[kb + j][dd];
#pragma unroll
        for (int i = 0; i < 4; i++)
#pragma unroll
            for (int j = 0; j < 4; j++)
                acc[i][j] = fmaf(a[i], c[j], acc[i][j]);
    }

    int m[4];
#pragma unroll
    for (int j = 0; j < 4; j++) m[j] = mask[(size_t)b * Ss + k0 + kb + j];

    const float scale = 0.125f;  // 1/sqrt(64)
    float rsum[4];
#pragma unroll
    for (int i = 0; i < 4; i++) {
        float4 o;
        o.x = m[0] ? expf(acc[i][0] * scale) : 0.f;
        o.y = m[1] ? expf(acc[i][1] * scale) : 0.f;
        o.z = m[2] ? expf(acc[i][2] * scale) : 0.f;
        o.w = m[3] ? expf(acc[i][3] * scale) : 0.f;
        rsum[i] = o.x + o.y + o.z + o.w;
        *(float4*)(P + ((size_t)bh * Ss + q0 + qb + i) * Ss + k0 + kb) = o;
    }
#pragma unroll
    for (int i = 0; i < 4; i++) red[qb + i][tx] = rsum[i];
    __syncthreads();

    if (tid < 64) {
        float s = 0.f;
#pragma unroll
        for (int t = 0; t < 16; t++) s += red[tid][t];
        atomicAdd(&g_rowsum[(size_t)bh * Ss + q0 + tid], s);
    }
}

// ---------------- normalize P rows (one block per row) ----------------
__global__ __launch_bounds__(256) void attn_normalize(float* __restrict__ P)
{
    const size_t row = blockIdx.x;               // B*H*S rows
    const float inv = 1.0f / g_rowsum[row];
    float4* p4 = (float4*)(P + row * Ss) + threadIdx.x;  // S/4 = 256 float4 per row
    float4 v = *p4;
    v.x *= inv; v.y *= inv; v.z *= inv; v.w *= inv;
    *p4 = v;
}

// ---------------- X = P @ V (per head) ----------------
__global__ __launch_bounds__(256) void attn_pv(
    const float* __restrict__ P, const float* __restrict__ V,
    float* __restrict__ X)
{
    __shared__ float Ps[64][33];
    __shared__ float Vs[32][64];

    const int bh = blockIdx.y;
    const int b = bh >> 4, h = bh & 15;
    const int q0 = blockIdx.x << 6;
    const int tid = threadIdx.x;
    const int ty = tid >> 4, tx = tid & 15;

    float acc[4][4];
#pragma unroll
    for (int i = 0; i < 4; i++)
#pragma unroll
        for (int j = 0; j < 4; j++) acc[i][j] = 0.f;

    for (int k0 = 0; k0 < Ss; k0 += 32) {
#pragma unroll
        for (int i = 0; i < 2; i++) {
            int id = tid + i * 256;
            int pr = id >> 3, pc = (id & 7) << 2;
            float4 pv = *(const float4*)(P + ((size_t)bh * Ss + q0 + pr) * Ss + k0 + pc);
            Ps[pr][pc + 0] = pv.x; Ps[pr][pc + 1] = pv.y;
            Ps[pr][pc + 2] = pv.z; Ps[pr][pc + 3] = pv.w;
            int vr = id >> 4, vc = (id & 15) << 2;
            *(float4*)&Vs[vr][vc] =
                *(const float4*)(V + ((size_t)b * Ss + k0 + vr) * Dd + h * HD + vc);
        }
        __syncthreads();
#pragma unroll 8
        for (int kk = 0; kk < 32; kk++) {
            float a[4];
#pragma unroll
            for (int i = 0; i < 4; i++) a[i] = Ps[ty * 4 + i][kk];
            float4 bv = *(float4*)&Vs[kk][tx << 2];
#pragma unroll
            for (int i = 0; i < 4; i++) {
                acc[i][0] = fmaf(a[i], bv.x, acc[i][0]);
                acc[i][1] = fmaf(a[i], bv.y, acc[i][1]);
                acc[i][2] = fmaf(a[i], bv.z, acc[i][2]);
                acc[i][3] = fmaf(a[i], bv.w, acc[i][3]);
            }
        }
        __syncthreads();
    }
#pragma unroll
    for (int i = 0; i < 4; i++) {
        float4 o = {acc[i][0], acc[i][1], acc[i][2], acc[i][3]};
        *(float4*)(X + ((size_t)b * Ss + q0 + ty * 4 + i) * Dd + h * HD + (tx << 2)) = o;
    }
}

// ---------------- launch ----------------
extern "C" void kernel_launch(void* const* d_in, const int* in_sizes, int n_in,
                              void* d_out, int out_size)
{
    const float* query = (const float*)d_in[0];
    const float* key   = (const float*)d_in[1];
    const float* value = (const float*)d_in[2];
    const int*   mask  = (const int*)d_in[3];
    const float* Wq = (const float*)d_in[4];  const float* bq = (const float*)d_in[5];
    const float* Wk = (const float*)d_in[6];  const float* bk = (const float*)d_in[7];
    const float* Wv = (const float*)d_in[8];  const float* bv = (const float*)d_in[9];
    const float* Wo = (const float*)d_in[10]; const float* bo = (const float*)d_in[11];

    float* out = (float*)d_out;
    const size_t BSD = (size_t)Bb * Ss * Dd;              // 4,194,304
    const size_t ATT = (size_t)BHt * Ss * Ss;             // 67,108,864

    void *pq, *pk, *pv, *px;
    cudaGetSymbolAddress(&pq, g_q);
    cudaGetSymbolAddress(&pk, g_k);
    cudaGetSymbolAddress(&pv, g_v);
    cudaGetSymbolAddress(&px, g_x);
    float* q = (float*)pq;
    float* k = (float*)pk;
    float* v = (float*)pv;
    float* x = (float*)px;

    float* P;
    if ((size_t)out_size >= BSD + ATT) {
        P = out + BSD;  // outputs first, attention second (tuple flatten order)
    } else {
        void* pp;
        cudaGetSymbolAddress(&pp, g_p_fallback);
        P = (float*)pp;
    }

    dim3 gemm_grid(Dd / 128, Mrows / 128);  // (8, 32)

    sgemm_bias<<<gemm_grid, 256>>>(query, Wq, bq, q, Mrows, Dd, Dd);
    sgemm_bias<<<gemm_grid, 256>>>(key,   Wk, bk, k, Mrows, Dd, Dd);
    sgemm_bias<<<gemm_grid, 256>>>(value, Wv, bv, v, Mrows, Dd, Dd);

    zero_rowsum<<<64, 1024>>>();

    attn_energy<<<dim3(Ss / 64, Ss / 64, BHt), 256>>>(q, k, mask, P);
    attn_normalize<<<BHt * Ss, 256>>>(P);
    attn_pv<<<dim3(Ss / 64, BHt), 256>>>(P, v, x);

    sgemm_bias<<<gemm_grid, 256>>>(x, Wo, bo, out, Mrows, Dd, Dd);
}

// round 2
// speedup vs baseline: 1.5582x; 1.5582x over previous
#include <cuda_runtime.h>
#include <cuda_bf16.h>
#include <math.h>
#include <stdint.h>

#define Bb 4
#define Ss 1024
#define Dd 1024
#define Hh 16
#define HD 64
#define BHt (Bb*Hh)
#define Mrows (Bb*Ss)

// ---------------- device scratch (no allocations allowed) ----------------
__device__ float g_q[(size_t)Bb*Ss*Dd];
__device__ float g_k[(size_t)Bb*Ss*Dd];
__device__ float g_v[(size_t)Bb*Ss*Dd];
__device__ float g_x[(size_t)Bb*Ss*Dd];
__device__ float g_rowsum[(size_t)BHt*Ss];
__device__ float g_p_fallback[(size_t)BHt*Ss*Ss];
__device__ __nv_bfloat16 g_ah[(size_t)Mrows*Dd];
__device__ __nv_bfloat16 g_al[(size_t)Mrows*Dd];
__device__ __nv_bfloat16 g_wh[(size_t)Dd*Dd];
__device__ __nv_bfloat16 g_wl[(size_t)Dd*Dd];

// ---------------- fp32 -> bf16 hi/lo split ----------------
__global__ __launch_bounds__(256) void split_bf16(
    const float* __restrict__ x, __nv_bfloat16* __restrict__ hi,
    __nv_bfloat16* __restrict__ lo)
{
    int i = blockIdx.x * blockDim.x + threadIdx.x;
    float4 v = ((const float4*)x)[i];
    __nv_bfloat16 h0 = __float2bfloat16(v.x);
    __nv_bfloat16 h1 = __float2bfloat16(v.y);
    __nv_bfloat16 h2 = __float2bfloat16(v.z);
    __nv_bfloat16 h3 = __float2bfloat16(v.w);
    __nv_bfloat16 l0 = __float2bfloat16(v.x - __bfloat162float(h0));
    __nv_bfloat16 l1 = __float2bfloat16(v.y - __bfloat162float(h1));
    __nv_bfloat16 l2 = __float2bfloat16(v.z - __bfloat162float(h2));
    __nv_bfloat16 l3 = __float2bfloat16(v.w - __bfloat162float(h3));
    __nv_bfloat162 ph0; ph0.x = h0; ph0.y = h1;
    __nv_bfloat162 ph1; ph1.x = h2; ph1.y = h3;
    __nv_bfloat162 pl0; pl0.x = l0; pl0.y = l1;
    __nv_bfloat162 pl1; pl1.x = l2; pl1.y = l3;
    ((__nv_bfloat162*)hi)[2*i]   = ph0;
    ((__nv_bfloat162*)hi)[2*i+1] = ph1;
    ((__nv_bfloat162*)lo)[2*i]   = pl0;
    ((__nv_bfloat162*)lo)[2*i+1] = pl1;
}

// ---------------- mma helpers ----------------
__device__ __forceinline__ uint32_t smem_u32(const void* p) {
    uint32_t a;
    asm("{ .reg .u64 t; cvta.to.shared.u64 t, %1; cvt.u32.u64 %0, t; }" : "=r"(a) : "l"(p));
    return a;
}
__device__ __forceinline__ void ldsm_x4(uint32_t* r, uint32_t addr) {
    asm volatile("ldmatrix.sync.aligned.m8n8.x4.shared.b16 {%0,%1,%2,%3}, [%4];"
                 : "=r"(r[0]), "=r"(r[1]), "=r"(r[2]), "=r"(r[3]) : "r"(addr));
}
__device__ __forceinline__ void ldsm_x2t(uint32_t* r, uint32_t addr) {
    asm volatile("ldmatrix.sync.aligned.m8n8.x2.trans.shared.b16 {%0,%1}, [%2];"
                 : "=r"(r[0]), "=r"(r[1]) : "r"(addr));
}
__device__ __forceinline__ void mma16816(float* c, const uint32_t* a, const uint32_t* b) {
    asm volatile(
        "mma.sync.aligned.m16n8k16.row.col.f32.bf16.bf16.f32 "
        "{%0,%1,%2,%3}, {%4,%5,%6,%7}, {%8,%9}, {%0,%1,%2,%3};"
        : "+f"(c[0]), "+f"(c[1]), "+f"(c[2]), "+f"(c[3])
        : "r"(a[0]), "r"(a[1]), "r"(a[2]), "r"(a[3]), "r"(b[0]), "r"(b[1]));
}

// --------- 128x128 tensor-core GEMM, C = Ah*Bh + Ah*Bl + Al*Bh + bias ---------
__global__ __launch_bounds__(256) void gemm_bf16x3_bias(
    const __nv_bfloat16* __restrict__ Ah, const __nv_bfloat16* __restrict__ Al,
    const __nv_bfloat16* __restrict__ Bh, const __nv_bfloat16* __restrict__ Bl,
    const float* __restrict__ bias, float* __restrict__ C,
    int Mn, int Nn, int Kn)
{
    // As: [row][0-31 hi | 32-63 lo] bf16, 128B rows, 16B chunks swizzled by chunk^(row&7)
    __shared__ __align__(16) __nv_bfloat16 As[128][64];
    // Bs: [hi/lo][k][n 0-127] bf16, 256B rows, chunks swizzled by chunk^(k&7)
    __shared__ __align__(16) __nv_bfloat16 Bs[2][32][128];

    const int tid = threadIdx.x;
    const int warp = tid >> 5, lane = tid & 31;
    const int wm = (warp >> 2) << 6;   // 0 / 64
    const int wn = (warp & 3) << 5;    // 0,32,64,96
    const int bm = blockIdx.y << 7, bn = blockIdx.x << 7;

    const uint32_t as0 = smem_u32(&As[0][0]);
    const uint32_t bs0 = smem_u32(&Bs[0][0][0]);

    float acc[4][4][4];
#pragma unroll
    for (int i = 0; i < 4; i++)
#pragma unroll
        for (int j = 0; j < 4; j++)
#pragma unroll
            for (int r = 0; r < 4; r++) acc[i][j][r] = 0.f;

    const int arow = tid >> 1, ahc = tid & 1;
    const __nv_bfloat16* gAh = Ah + (size_t)(bm + arow) * Kn + ahc * 16;
    const __nv_bfloat16* gAl = Al + (size_t)(bm + arow) * Kn + ahc * 16;
    const int bk = tid >> 3, bc = (tid & 7) << 1;
    const __nv_bfloat16* gBh = Bh + (size_t)bk * Nn + bn + (bc << 3);
    const __nv_bfloat16* gBl = Bl + (size_t)bk * Nn + bn + (bc << 3);

    char* apB = (char*)(&As[0][0]) + arow * 128;
    char* bpB = (char*)(&Bs[0][0][0]) + bk * 256;
    const int swa = arow & 7, swb = bk & 7;

    for (int k0 = 0; k0 < Kn; k0 += 32) {
        uint4 va0 = *(const uint4*)(gAh + k0);
        uint4 va1 = *(const uint4*)(gAh + k0 + 8);
        uint4 va2 = *(const uint4*)(gAl + k0);
        uint4 va3 = *(const uint4*)(gAl + k0 + 8);
        uint4 vb0 = *(const uint4*)(gBh + (size_t)k0 * Nn);
        uint4 vb1 = *(const uint4*)(gBh + (size_t)k0 * Nn + 8);
        uint4 vb2 = *(const uint4*)(gBl + (size_t)k0 * Nn);
        uint4 vb3 = *(const uint4*)(gBl + (size_t)k0 * Nn + 8);
        __syncthreads();
        *(uint4*)(apB + ((((ahc << 1) | 0) ^ swa) << 4)) = va0;
        *(uint4*)(apB + ((((ahc << 1) | 1) ^ swa) << 4)) = va1;
        *(uint4*)(apB + (((((ahc << 1) | 0) + 4) ^ swa) << 4)) = va2;
        *(uint4*)(apB + (((((ahc << 1) | 1) + 4) ^ swa) << 4)) = va3;
        *(uint4*)(bpB + (((bc | 0) ^ swb) << 4)) = vb0;
        *(uint4*)(bpB + (((bc | 1) ^ swb) << 4)) = vb1;
        *(uint4*)(bpB + 8192 + (((bc | 0) ^ swb) << 4)) = vb2;
        *(uint4*)(bpB + 8192 + (((bc | 1) ^ swb) << 4)) = vb3;
        __syncthreads();

#pragma unroll
        for (int ks = 0; ks < 2; ks++) {
            uint32_t af[2][4][4];
            uint32_t bf[2][4][2];
            const int r15 = lane & 15;
            const int choff = (ks << 1) + (lane >> 4);
#pragma unroll
            for (int mf = 0; mf < 4; mf++) {
                int row = wm + (mf << 4) + r15;
                uint32_t base = as0 + row * 128;
                int sw = row & 7;
                ldsm_x4(af[0][mf], base + ((choff ^ sw) << 4));
                ldsm_x4(af[1][mf], base + (((choff + 4) ^ sw) << 4));
            }
            const int krow = (ks << 4) + r15;
            const int swk = krow & 7;
#pragma unroll
            for (int nf = 0; nf < 4; nf++) {
                int chunk = (wn + (nf << 3)) >> 3;
                uint32_t ad = bs0 + krow * 256 + ((chunk ^ swk) << 4);
                ldsm_x2t(bf[0][nf], ad);
                ldsm_x2t(bf[1][nf], ad + 8192);
            }
#pragma unroll
            for (int mf = 0; mf < 4; mf++)
#pragma unroll
                for (int nf = 0; nf < 4; nf++) {
                    mma16816(acc[mf][nf], af[0][mf], bf[0][nf]);
                    mma16816(acc[mf][nf], af[0][mf], bf[1][nf]);
                    mma16816(acc[mf][nf], af[1][mf], bf[0][nf]);
                }
        }
    }

    const int gr = lane >> 2, gc = (lane & 3) << 1;
#pragma unroll
    for (int mf = 0; mf < 4; mf++) {
        int r0 = bm + wm + (mf << 4) + gr;
#pragma unroll
        for (int nf = 0; nf < 4; nf++) {
            int col = bn + wn + (nf << 3) + gc;
            float2 bv = *(const float2*)(bias + col);
            float2 o0 = {acc[mf][nf][0] + bv.x, acc[mf][nf][1] + bv.y};
            float2 o1 = {acc[mf][nf][2] + bv.x, acc[mf][nf][3] + bv.y};
            *(float2*)(C + (size_t)r0 * Nn + col) = o0;
            *(float2*)(C + (size_t)(r0 + 8) * Nn + col) = o1;
        }
    }
}

// ---------------- zero rowsums ----------------
__global__ void zero_rowsum()
{
    g_rowsum[(size_t)blockIdx.x * 1024 + threadIdx.x] = 0.f;
}

// ---- QK^T/8 + mask + exp, write unnormalized P, accumulate rowsums ----
__global__ __launch_bounds__(256) void attn_energy(
    const float* __restrict__ Q, const float* __restrict__ Kt,
    const int* __restrict__ mask, float* __restrict__ P)
{
    __shared__ float Qs[64][68];   // [q][d]
    __shared__ float Ks[64][68];   // [d][k]  (transposed K tile)
    __shared__ float red[64][17];

    const int bh = blockIdx.z;
    const int b = bh >> 4, h = bh & 15;
    const int q0 = blockIdx.y << 6;
    const int k0 = blockIdx.x << 6;
    const int tid = threadIdx.x;

    const float* Qb = Q + ((size_t)b * Ss + q0) * Dd + h * HD;
    const float* Kb = Kt + ((size_t)b * Ss + k0) * Dd + h * HD;

#pragma unroll
    for (int i = 0; i < 4; i++) {
        int id = tid + i * 256;
        int row = id >> 4, col = (id & 15) << 2;
        float4 qv = *(const float4*)(Qb + (size_t)row * Dd + col);
        *(float4*)&Qs[row][col] = qv;
        float4 kv = *(const float4*)(Kb + (size_t)row * Dd + col);
        Ks[col + 0][row] = kv.x; Ks[col + 1][row] = kv.y;
        Ks[col + 2][row] = kv.z; Ks[col + 3][row] = kv.w;
    }
    __syncthreads();

    const int ty = tid >> 4, tx = tid & 15;
    const int qb = ty << 2, kb = tx << 2;

    float acc[4][4];
#pragma unroll
    for (int i = 0; i < 4; i++)
#pragma unroll
        for (int j = 0; j < 4; j++) acc[i][j] = 0.f;

#pragma unroll 4
    for (int dd = 0; dd < 64; dd += 4) {
        float a4[4][4], c4[4][4];
#pragma unroll
        for (int i = 0; i < 4; i++) {
            float4 t = *(float4*)&Qs[qb + i][dd];
            a4[i][0] = t.x; a4[i][1] = t.y; a4[i][2] = t.z; a4[i][3] = t.w;
        }
#pragma unroll
        for (int r = 0; r < 4; r++) {
            float4 t = *(float4*)&Ks[dd + r][kb];
            c4[r][0] = t.x; c4[r][1] = t.y; c4[r][2] = t.z; c4[r][3] = t.w;
        }
#pragma unroll
        for (int i = 0; i < 4; i++)
#pragma unroll
            for (int r = 0; r < 4; r++)
#pragma unroll
                for (int j = 0; j < 4; j++)
                    acc[i][j] = fmaf(a4[i][r], c4[r][j], acc[i][j]);
    }

    int m[4];
#pragma unroll
    for (int j = 0; j < 4; j++) m[j] = mask[(size_t)b * Ss + k0 + kb + j];

    const float scale = 0.125f;  // 1/sqrt(64)
    float rsum[4];
#pragma unroll
    for (int i = 0; i < 4; i++) {
        float4 o;
        o.x = m[0] ? __expf(acc[i][0] * scale) : 0.f;
        o.y = m[1] ? __expf(acc[i][1] * scale) : 0.f;
        o.z = m[2] ? __expf(acc[i][2] * scale) : 0.f;
        o.w = m[3] ? __expf(acc[i][3] * scale) : 0.f;
        rsum[i] = o.x + o.y + o.z + o.w;
        *(float4*)(P + ((size_t)bh * Ss + q0 + qb + i) * Ss + k0 + kb) = o;
    }
#pragma unroll
    for (int i = 0; i < 4; i++) red[qb + i][tx] = rsum[i];
    __syncthreads();

    if (tid < 64) {
        float s = 0.f;
#pragma unroll
        for (int t = 0; t < 16; t++) s += red[tid][t];
        atomicAdd(&g_rowsum[(size_t)bh * Ss + q0 + tid], s);
    }
}

// ---------------- normalize P rows ----------------
__global__ __launch_bounds__(256) void attn_normalize(float* __restrict__ P)
{
    const size_t row = blockIdx.x;
    const float inv = 1.0f / g_rowsum[row];
    float4* p4 = (float4*)(P + row * Ss) + threadIdx.x;
    float4 v = *p4;
    v.x *= inv; v.y *= inv; v.z *= inv; v.w *= inv;
    *p4 = v;
}

// ---------------- X = P @ V (per head) ----------------
__global__ __launch_bounds__(256) void attn_pv(
    const float* __restrict__ P, const float* __restrict__ V,
    float* __restrict__ X)
{
    __shared__ float Ps[64][36];
    __shared__ float Vs[32][68];

    const int bh = blockIdx.y;
    const int b = bh >> 4, h = bh & 15;
    const int q0 = blockIdx.x << 6;
    const int tid = threadIdx.x;
    const int ty = tid >> 4, tx = tid & 15;
    const int qb = ty << 2;

    float acc[4][4];
#pragma unroll
    for (int i = 0; i < 4; i++)
#pragma unroll
        for (int j = 0; j < 4; j++) acc[i][j] = 0.f;

    for (int k0 = 0; k0 < Ss; k0 += 32) {
#pragma unroll
        for (int i = 0; i < 2; i++) {
            int id = tid + i * 256;
            int pr = id >> 3, pc = (id & 7) << 2;
            float4 pv = *(const float4*)(P + ((size_t)bh * Ss + q0 + pr) * Ss + k0 + pc);
            *(float4*)&Ps[pr][pc] = pv;
            int vr = id >> 4, vc = (id & 15) << 2;
            *(float4*)&Vs[vr][vc] =
                *(const float4*)(V + ((size_t)b * Ss + k0 + vr) * Dd + h * HD + vc);
        }
        __syncthreads();
#pragma unroll 4
        for (int kk = 0; kk < 32; kk += 4) {
            float a4[4][4], c4[4][4];
#pragma unroll
            for (int i = 0; i < 4; i++) {
                float4 t = *(float4*)&Ps[qb + i][kk];
                a4[i][0] = t.x; a4[i][1] = t.y; a4[i][2] = t.z; a4[i][3] = t.w;
            }
#pragma unroll
            for (int r = 0; r < 4; r++) {
                float4 t = *(float4*)&Vs[kk + r][tx << 2];
                c4[r][0] = t.x; c4[r][1] = t.y; c4[r][2] = t.z; c4[r][3] = t.w;
            }
#pragma unroll
            for (int i = 0; i < 4; i++)
#pragma unroll
                for (int r = 0; r < 4; r++)
#pragma unroll
                    for (int j = 0; j < 4; j++)
                        acc[i][j] = fmaf(a4[i][r], c4[r][j], acc[i][j]);
        }
        __syncthreads();
    }
#pragma unroll
    for (int i = 0; i < 4; i++) {
        float4 o = {acc[i][0], acc[i][1], acc[i][2], acc[i][3]};
        *(float4*)(X + ((size_t)b * Ss + q0 + qb + i) * Dd + h * HD + (tx << 2)) = o;
    }
}

// ---------------- launch ----------------
extern "C" void kernel_launch(void* const* d_in, const int* in_sizes, int n_in,
                              void* d_out, int out_size)
{
    const float* query = (const float*)d_in[0];
    const float* key   = (const float*)d_in[1];
    const float* value = (const float*)d_in[2];
    const int*   mask  = (const int*)d_in[3];
    const float* Wq = (const float*)d_in[4];  const float* bq = (const float*)d_in[5];
    const float* Wk = (const float*)d_in[6];  const float* bk = (const float*)d_in[7];
    const float* Wv = (const float*)d_in[8];  const float* bv = (const float*)d_in[9];
    const float* Wo = (const float*)d_in[10]; const float* bo = (const float*)d_in[11];

    float* out = (float*)d_out;
    const size_t BSD = (size_t)Bb * Ss * Dd;
    const size_t ATT = (size_t)BHt * Ss * Ss;

    void *pq, *pk, *pv, *px, *pah, *pal, *pwh, *pwl;
    cudaGetSymbolAddress(&pq, g_q);
    cudaGetSymbolAddress(&pk, g_k);
    cudaGetSymbolAddress(&pv, g_v);
    cudaGetSymbolAddress(&px, g_x);
    cudaGetSymbolAddress(&pah, g_ah);
    cudaGetSymbolAddress(&pal, g_al);
    cudaGetSymbolAddress(&pwh, g_wh);
    cudaGetSymbolAddress(&pwl, g_wl);
    float* q = (float*)pq;
    float* k = (float*)pk;
    float* v = (float*)pv;
    float* x = (float*)px;
    __nv_bfloat16* ah = (__nv_bfloat16*)pah;
    __nv_bfloat16* al = (__nv_bfloat16*)pal;
    __nv_bfloat16* wh = (__nv_bfloat16*)pwh;
    __nv_bfloat16* wl = (__nv_bfloat16*)pwl;

    float* P;
    if ((size_t)out_size >= BSD + ATT) {
        P = out + BSD;
    } else {
        void* pp;
        cudaGetSymbolAddress(&pp, g_p_fallback);
        P = (float*)pp;
    }

    dim3 gemm_grid(Dd / 128, Mrows / 128);  // (8, 32)
    const int nA4 = Mrows * Dd / 4;  // float4 count for activations
    const int nW4 = Dd * Dd / 4;

    // Q projection
    split_bf16<<<nA4 / 256, 256>>>(query, ah, al);
    split_bf16<<<nW4 / 256, 256>>>(Wq, wh, wl);
    gemm_bf16x3_bias<<<gemm_grid, 256>>>(ah, al, wh, wl, bq, q, Mrows, Dd, Dd);
    // K projection
    split_bf16<<<nA4 / 256, 256>>>(key, ah, al);
    split_bf16<<<nW4 / 256, 256>>>(Wk, wh, wl);
    gemm_bf16x3_bias<<<gemm_grid, 256>>>(ah, al, wh, wl, bk, k, Mrows, Dd, Dd);
    // V projection
    split_bf16<<<nA4 / 256, 256>>>(value, ah, al);
    split_bf16<<<nW4 / 256, 256>>>(Wv, wh, wl);
    gemm_bf16x3_bias<<<gemm_grid, 256>>>(ah, al, wh, wl, bv, v, Mrows, Dd, Dd);

    zero_rowsum<<<64, 1024>>>();
    attn_energy<<<dim3(Ss / 64, Ss / 64, BHt), 256>>>(q, k, mask, P);
    attn_normalize<<<BHt * Ss, 256>>>(P);
    attn_pv<<<dim3(Ss / 64, BHt), 256>>>(P, v, x);

    // Output projection
    split_bf16<<<nA4 / 256, 256>>>(x, ah, al);
    split_bf16<<<nW4 / 256, 256>>>(Wo, wh, wl);
    gemm_bf16x3_bias<<<gemm_grid, 256>>>(ah, al, wh, wl, bo, out, Mrows, Dd, Dd);
}

// round 3
// speedup vs baseline: 2.0940x; 1.3438x over previous
#include <cuda_runtime.h>
#include <cuda_bf16.h>
#include <math.h>
#include <stdint.h>

#define Bb 4
#define Ss 1024
#define Dd 1024
#define Hh 16
#define HD 64
#define BHt (Bb*Hh)
#define Mrows (Bb*Ss)

// ---------------- device scratch ----------------
__device__ __nv_bfloat16 g_qh[(size_t)Mrows*Dd];
__device__ __nv_bfloat16 g_ql[(size_t)Mrows*Dd];
__device__ __nv_bfloat16 g_kh[(size_t)Mrows*Dd];
__device__ __nv_bfloat16 g_kl[(size_t)Mrows*Dd];
__device__ __nv_bfloat16 g_vh[(size_t)Mrows*Dd];
__device__ __nv_bfloat16 g_vl[(size_t)Mrows*Dd];
__device__ float g_x[(size_t)Mrows*Dd];
__device__ float g_rowsum[(size_t)BHt*Ss];
__device__ float g_p_fallback[(size_t)BHt*Ss*Ss];

// ---------------- helpers ----------------
__device__ __forceinline__ uint32_t smem_u32(const void* p) {
    uint32_t a;
    asm("{ .reg .u64 t; cvta.to.shared.u64 t, %1; cvt.u32.u64 %0, t; }" : "=r"(a) : "l"(p));
    return a;
}
__device__ __forceinline__ void ldsm_x4(uint32_t* r, uint32_t addr) {
    asm volatile("ldmatrix.sync.aligned.m8n8.x4.shared.b16 {%0,%1,%2,%3}, [%4];"
                 : "=r"(r[0]), "=r"(r[1]), "=r"(r[2]), "=r"(r[3]) : "r"(addr));
}
__device__ __forceinline__ void ldsm_x2t(uint32_t* r, uint32_t addr) {
    asm volatile("ldmatrix.sync.aligned.m8n8.x2.trans.shared.b16 {%0,%1}, [%2];"
                 : "=r"(r[0]), "=r"(r[1]) : "r"(addr));
}
__device__ __forceinline__ void mma16816(float* c, const uint32_t* a, const uint32_t* b) {
    asm volatile(
        "mma.sync.aligned.m16n8k16.row.col.f32.bf16.bf16.f32 "
        "{%0,%1,%2,%3}, {%4,%5,%6,%7}, {%8,%9}, {%0,%1,%2,%3};"
        : "+f"(c[0]), "+f"(c[1]), "+f"(c[2]), "+f"(c[3])
        : "r"(a[0]), "r"(a[1]), "r"(a[2]), "r"(a[3]), "r"(b[0]), "r"(b[1]));
}
// split two floats into packed bf16 hi pair + lo pair
__device__ __forceinline__ void split2(float x, float y, uint32_t& h, uint32_t& l) {
    __nv_bfloat16 hx = __float2bfloat16_rn(x);
    __nv_bfloat16 hy = __float2bfloat16_rn(y);
    __nv_bfloat162 hp; hp.x = hx; hp.y = hy;
    __nv_bfloat162 lp;
    lp.x = __float2bfloat16_rn(x - __bfloat162float(hx));
    lp.y = __float2bfloat16_rn(y - __bfloat162float(hy));
    h = *(uint32_t*)&hp;
    l = *(uint32_t*)&lp;
}
__device__ __forceinline__ void split8(const float4 a, const float4 b, uint4& h, uint4& l) {
    split2(a.x, a.y, h.x, l.x);
    split2(a.z, a.w, h.y, l.y);
    split2(b.x, b.y, h.z, l.z);
    split2(b.z, b.w, h.w, l.w);
}

// --------- 128x128 GEMM: fp32 in, in-kernel hi/lo split, 3-term MMA ---------
// mode 0: Cf = acc + bias (fp32). mode 1: (Ch,Cl) = bf16 split of acc+bias.
__global__ __launch_bounds__(256) void gemm_f32_tc(
    const float* __restrict__ A, const float* __restrict__ W,
    const float* __restrict__ bias,
    float* __restrict__ Cf, __nv_bfloat16* __restrict__ Ch,
    __nv_bfloat16* __restrict__ Cl, int mode,
    int Mn, int Nn, int Kn)
{
    __shared__ __align__(16) __nv_bfloat16 As[128][64];     // [row][hi 0-31 | lo 32-63]
    __shared__ __align__(16) __nv_bfloat16 Bs[2][32][128];  // [hi/lo][k][n]

    const int tid = threadIdx.x;
    const int warp = tid >> 5, lane = tid & 31;
    const int wm = (warp >> 2) << 6;
    const int wn = (warp & 3) << 5;
    const int bm = blockIdx.y << 7, bn = blockIdx.x << 7;

    const uint32_t as0 = smem_u32(&As[0][0]);
    const uint32_t bs0 = smem_u32(&Bs[0][0][0]);

    float acc[4][4][4];
#pragma unroll
    for (int i = 0; i < 4; i++)
#pragma unroll
        for (int j = 0; j < 4; j++)
#pragma unroll
            for (int r = 0; r < 4; r++) acc[i][j][r] = 0.f;

    const int arow = tid >> 1, acol = (tid & 1) << 4;
    const float* gA = A + (size_t)(bm + arow) * Kn + acol;
    const int bk = tid >> 3, bcol = (tid & 7) << 4;
    const float* gW = W + (size_t)bk * Nn + bn + bcol;

    char* apB = (char*)(&As[0][0]) + arow * 128;
    char* bpB = (char*)(&Bs[0][0][0]) + bk * 256;
    const int swa = arow & 7, swb = bk & 7;
    const int ac0 = (tid & 1) << 1;   // A hi chunks ac0, ac0+1 ; lo +4
    const int bc0 = (tid & 7) << 1;   // B chunks bc0, bc0+1

    for (int k0 = 0; k0 < Kn; k0 += 32) {
        float4 fa0 = *(const float4*)(gA + k0);
        float4 fa1 = *(const float4*)(gA + k0 + 4);
        float4 fa2 = *(const float4*)(gA + k0 + 8);
        float4 fa3 = *(const float4*)(gA + k0 + 12);
        float4 fw0 = *(const float4*)(gW + (size_t)k0 * Nn);
        float4 fw1 = *(const float4*)(gW + (size_t)k0 * Nn + 4);
        float4 fw2 = *(const float4*)(gW + (size_t)k0 * Nn + 8);
        float4 fw3 = *(const float4*)(gW + (size_t)k0 * Nn + 12);
        uint4 ah0, al0, ah1, al1, wh0, wl0, wh1, wl1;
        split8(fa0, fa1, ah0, al0);
        split8(fa2, fa3, ah1, al1);
        split8(fw0, fw1, wh0, wl0);
        split8(fw2, fw3, wh1, wl1);
        __syncthreads();
        *(uint4*)(apB + (((ac0 | 0) ^ swa) << 4)) = ah0;
        *(uint4*)(apB + (((ac0 | 1) ^ swa) << 4)) = ah1;
        *(uint4*)(apB + ((((ac0 | 0) + 4) ^ swa) << 4)) = al0;
        *(uint4*)(apB + ((((ac0 | 1) + 4) ^ swa) << 4)) = al1;
        *(uint4*)(bpB + (((bc0 | 0) ^ swb) << 4)) = wh0;
        *(uint4*)(bpB + (((bc0 | 1) ^ swb) << 4)) = wh1;
        *(uint4*)(bpB + 8192 + (((bc0 | 0) ^ swb) << 4)) = wl0;
        *(uint4*)(bpB + 8192 + (((bc0 | 1) ^ swb) << 4)) = wl1;
        __syncthreads();

#pragma unroll
        for (int ks = 0; ks < 2; ks++) {
            uint32_t af[2][4][4];
            uint32_t bf[2][4][2];
            const int r15 = lane & 15;
            const int choff = (ks << 1) + (lane >> 4);
#pragma unroll
            for (int mf = 0; mf < 4; mf++) {
                int row = wm + (mf << 4) + r15;
                uint32_t base = as0 + row * 128;
                int sw = row & 7;
                ldsm_x4(af[0][mf], base + ((choff ^ sw) << 4));
                ldsm_x4(af[1][mf], base + (((choff + 4) ^ sw) << 4));
            }
            const int krow = (ks << 4) + r15;
            const int swk = krow & 7;
#pragma unroll
            for (int nf = 0; nf < 4; nf++) {
                int chunk = (wn + (nf << 3)) >> 3;
                uint32_t ad = bs0 + krow * 256 + ((chunk ^ swk) << 4);
                ldsm_x2t(bf[0][nf], ad);
                ldsm_x2t(bf[1][nf], ad + 8192);
            }
#pragma unroll
            for (int mf = 0; mf < 4; mf++)
#pragma unroll
                for (int nf = 0; nf < 4; nf++) {
                    mma16816(acc[mf][nf], af[0][mf], bf[0][nf]);
                    mma16816(acc[mf][nf], af[0][mf], bf[1][nf]);
                    mma16816(acc[mf][nf], af[1][mf], bf[0][nf]);
                }
        }
    }

    const int gr = lane >> 2, gc = (lane & 3) << 1;
#pragma unroll
    for (int mf = 0; mf < 4; mf++) {
        int r0 = bm + wm + (mf << 4) + gr;
#pragma unroll
        for (int nf = 0; nf < 4; nf++) {
            int col = bn + wn + (nf << 3) + gc;
            float2 bv = *(const float2*)(bias + col);
            float c00 = acc[mf][nf][0] + bv.x, c01 = acc[mf][nf][1] + bv.y;
            float c10 = acc[mf][nf][2] + bv.x, c11 = acc[mf][nf][3] + bv.y;
            if (mode == 0) {
                *(float2*)(Cf + (size_t)r0 * Nn + col) = make_float2(c00, c01);
                *(float2*)(Cf + (size_t)(r0 + 8) * Nn + col) = make_float2(c10, c11);
            } else {
                uint32_t h, l;
                split2(c00, c01, h, l);
                *(uint32_t*)(Ch + (size_t)r0 * Nn + col) = h;
                *(uint32_t*)(Cl + (size_t)r0 * Nn + col) = l;
                split2(c10, c11, h, l);
                *(uint32_t*)(Ch + (size_t)(r0 + 8) * Nn + col) = h;
                *(uint32_t*)(Cl + (size_t)(r0 + 8) * Nn + col) = l;
            }
        }
    }
}

// ---- tensor-core energy: P = exp(mask ? QK^T/8 : -inf), rowsums ----
__global__ __launch_bounds__(256) void attn_energy_tc(
    const __nv_bfloat16* __restrict__ qh, const __nv_bfloat16* __restrict__ ql,
    const __nv_bfloat16* __restrict__ kh, const __nv_bfloat16* __restrict__ kl,
    const int* __restrict__ mask, float* __restrict__ P)
{
    __shared__ __align__(16) __nv_bfloat16 Qh[64][64], Ql[64][64];
    __shared__ __align__(16) __nv_bfloat16 Kh[64][64], Kl[64][64];
    __shared__ float red[64][4];

    const int tid = threadIdx.x;
    const int warp = tid >> 5, lane = tid & 31;
    const int wm = (warp >> 2) << 5;   // 0 / 32
    const int wn = (warp & 3) << 4;    // 0,16,32,48
    const int bh = blockIdx.y;
    const int b = bh >> 4, h = bh & 15;
    const int q0 = blockIdx.x << 6;

    const uint32_t qh0 = smem_u32(&Qh[0][0]);
    const uint32_t ql0 = smem_u32(&Ql[0][0]);
    const uint32_t kh0 = smem_u32(&Kh[0][0]);
    const uint32_t kl0 = smem_u32(&Kl[0][0]);

    // load Q tile (rows q0..q0+63, cols h*64..h*64+63)
    {
        int row = tid >> 2;
        int c0 = (tid & 3) << 1;
        const size_t base = ((size_t)(b * Ss + q0 + row)) * Dd + h * HD;
#pragma unroll
        for (int i = 0; i < 2; i++) {
            int c = c0 + i;
            int swc = (c ^ (row & 7)) << 3;
            *(uint4*)&Qh[row][swc] = *(const uint4*)(qh + base + (c << 3));
            *(uint4*)&Ql[row][swc] = *(const uint4*)(ql + base + (c << 3));
        }
    }

    float rs[2][2] = {{0.f, 0.f}, {0.f, 0.f}};
    const int gr = lane >> 2, gc = (lane & 3) << 1;
    const float sc = 0.125f;

    for (int kt = 0; kt < 16; kt++) {
        const int k0 = kt << 6;
        __syncthreads();
        {
            int row = tid >> 2;
            int c0 = (tid & 3) << 1;
            const size_t base = ((size_t)(b * Ss + k0 + row)) * Dd + h * HD;
#pragma unroll
            for (int i = 0; i < 2; i++) {
                int c = c0 + i;
                int swc = (c ^ (row & 7)) << 3;
                *(uint4*)&Kh[row][swc] = *(const uint4*)(kh + base + (c << 3));
                *(uint4*)&Kl[row][swc] = *(const uint4*)(kl + base + (c << 3));
            }
        }
        __syncthreads();

        float eacc[2][2][4];
#pragma unroll
        for (int i = 0; i < 2; i++)
#pragma unroll
            for (int j = 0; j < 2; j++)
#pragma unroll
                for (int r = 0; r < 4; r++) eacc[i][j][r] = 0.f;

#pragma unroll
        for (int ks = 0; ks < 4; ks++) {
            const int r15 = lane & 15;
            const int choff = (ks << 1) + (lane >> 4);
            uint32_t aH[2][4], aL[2][4];
#pragma unroll
            for (int mf = 0; mf < 2; mf++) {
                int row = wm + (mf << 4) + r15;
                int off = row * 128 + ((choff ^ (row & 7)) << 4);
                ldsm_x4(aH[mf], qh0 + off);
                ldsm_x4(aL[mf], ql0 + off);
            }
            // B frags from K[n][k] row-major via non-trans x4:
            // lanes0-7: n0-7 chunk ks*2; 8-15: n0-7 chunk ks*2+1; 16-23: n8-15 c0; 24-31: n8-15 c1
            int nrow = wn + ((lane >> 4) << 3) + (lane & 7);
            int kch = (ks << 1) + ((lane >> 3) & 1);
            int boff = nrow * 128 + ((kch ^ (nrow & 7)) << 4);
            uint32_t bH[4], bL[4];
            ldsm_x4(bH, kh0 + boff);
            ldsm_x4(bL, kl0 + boff);
#pragma unroll
            for (int mf = 0; mf < 2; mf++)
#pragma unroll
                for (int nf = 0; nf < 2; nf++) {
                    mma16816(eacc[mf][nf], aH[mf], bH + nf * 2);
                    mma16816(eacc[mf][nf], aH[mf], bL + nf * 2);
                    mma16816(eacc[mf][nf], aL[mf], bH + nf * 2);
                }
        }

        // epilogue: exp + mask, write P, accumulate rowsums
#pragma unroll
        for (int mf = 0; mf < 2; mf++) {
            int row0 = q0 + wm + (mf << 4) + gr;
#pragma unroll
            for (int nf = 0; nf < 2; nf++) {
                int col = k0 + wn + (nf << 3) + gc;
                int m0 = mask[b * Ss + col];
                int m1 = mask[b * Ss + col + 1];
                float e0 = m0 ? __expf(eacc[mf][nf][0] * sc) : 0.f;
                float e1 = m1 ? __expf(eacc[mf][nf][1] * sc) : 0.f;
                float e2 = m0 ? __expf(eacc[mf][nf][2] * sc) : 0.f;
                float e3 = m1 ? __expf(eacc[mf][nf][3] * sc) : 0.f;
                rs[mf][0] += e0 + e1;
                rs[mf][1] += e2 + e3;
                *(float2*)(P + ((size_t)bh * Ss + row0) * Ss + col) = make_float2(e0, e1);
                *(float2*)(P + ((size_t)bh * Ss + row0 + 8) * Ss + col) = make_float2(e2, e3);
            }
        }
    }

    // rowsum reduce: shfl over lane&3, then cross-warp via smem
#pragma unroll
    for (int mf = 0; mf < 2; mf++)
#pragma unroll
        for (int hf = 0; hf < 2; hf++) {
            float v = rs[mf][hf];
            v += __shfl_xor_sync(0xffffffff, v, 1);
            v += __shfl_xor_sync(0xffffffff, v, 2);
            if ((lane & 3) == 0)
                red[wm + (mf << 4) + gr + (hf << 3)][warp & 3] = v;
        }
    __syncthreads();
    if (tid < 64) {
        float s = red[tid][0] + red[tid][1] + red[tid][2] + red[tid][3];
        g_rowsum[(size_t)bh * Ss + q0 + tid] = s;
    }
}

// ---- fused normalize + P write + X = P@V (tensor core) ----
__global__ __launch_bounds__(256) void attn_pv_tc(
    float* __restrict__ P,
    const __nv_bfloat16* __restrict__ vh, const __nv_bfloat16* __restrict__ vl,
    float* __restrict__ X)
{
    __shared__ __align__(16) __nv_bfloat16 Ph[64][64], Pl[64][64];
    __shared__ __align__(16) __nv_bfloat16 Vh[64][64], Vl[64][64];
    __shared__ float sinv[64];

    const int tid = threadIdx.x;
    const int warp = tid >> 5, lane = tid & 31;
    const int wm = (warp >> 2) << 5;
    const int wn = (warp & 3) << 4;
    const int bh = blockIdx.y;
    const int b = bh >> 4, h = bh & 15;
    const int q0 = blockIdx.x << 6;

    const uint32_t ph0 = smem_u32(&Ph[0][0]);
    const uint32_t pl0 = smem_u32(&Pl[0][0]);
    const uint32_t vh0 = smem_u32(&Vh[0][0]);
    const uint32_t vl0 = smem_u32(&Vl[0][0]);

    if (tid < 64)
        sinv[tid] = 1.0f / g_rowsum[(size_t)bh * Ss + q0 + tid];

    float acc[2][2][4];
#pragma unroll
    for (int i = 0; i < 2; i++)
#pragma unroll
        for (int j = 0; j < 2; j++)
#pragma unroll
            for (int r = 0; r < 4; r++) acc[i][j][r] = 0.f;

    const int prow = tid >> 2;
    const int pc0 = (tid & 3) << 4;       // 16 floats per thread
    const int pch0 = (tid & 3) << 1;      // 2 chunks of 8

    for (int kt = 0; kt < 16; kt++) {
        const int k0 = kt << 6;
        __syncthreads();
        // V tile (rows = key pos, cols = hd), swizzled, like GEMM B
        {
            int row = tid >> 2;
            int c0 = (tid & 3) << 1;
            const size_t base = ((size_t)(b * Ss + k0 + row)) * Dd + h * HD;
#pragma unroll
            for (int i = 0; i < 2; i++) {
                int c = c0 + i;
                int swc = (c ^ (row & 7)) << 3;
                *(uint4*)&Vh[row][swc] = *(const uint4*)(vh + base + (c << 3));
                *(uint4*)&Vl[row][swc] = *(const uint4*)(vl + base + (c << 3));
            }
        }
        // P tile: read, normalize, write back, split into smem
        {
            float* prow_g = P + ((size_t)bh * Ss + q0 + prow) * Ss + k0 + pc0;
            float inv = sinv[prow];
            float4 p0 = *(float4*)(prow_g);
            float4 p1 = *(float4*)(prow_g + 4);
            float4 p2 = *(float4*)(prow_g + 8);
            float4 p3 = *(float4*)(prow_g + 12);
            p0.x *= inv; p0.y *= inv; p0.z *= inv; p0.w *= inv;
            p1.x *= inv; p1.y *= inv; p1.z *= inv; p1.w *= inv;
            p2.x *= inv; p2.y *= inv; p2.z *= inv; p2.w *= inv;
            p3.x *= inv; p3.y *= inv; p3.z *= inv; p3.w *= inv;
            *(float4*)(prow_g) = p0;
            *(float4*)(prow_g + 4) = p1;
            *(float4*)(prow_g + 8) = p2;
            *(float4*)(prow_g + 12) = p3;
            uint4 h0, l0, h1, l1;
            split8(p0, p1, h0, l0);
            split8(p2, p3, h1, l1);
            int sw0 = ((pch0 | 0) ^ (prow & 7)) << 3;
            int sw1 = ((pch0 | 1) ^ (prow & 7)) << 3;
            *(uint4*)&Ph[prow][sw0] = h0;
            *(uint4*)&Ph[prow][sw1] = h1;
            *(uint4*)&Pl[prow][sw0] = l0;
            *(uint4*)&Pl[prow][sw1] = l1;
        }
        __syncthreads();

#pragma unroll
        for (int ks = 0; ks < 4; ks++) {
            const int r15 = lane & 15;
            const int choff = (ks << 1) + (lane >> 4);
            uint32_t aH[2][4], aL[2][4];
#pragma unroll
            for (int mf = 0; mf < 2; mf++) {
                int row = wm + (mf << 4) + r15;
                int off = row * 128 + ((choff ^ (row & 7)) << 4);
                ldsm_x4(aH[mf], ph0 + off);
                ldsm_x4(aL[mf], pl0 + off);
            }
            const int krow = (ks << 4) + r15;
            const int swk = krow & 7;
            uint32_t bH[2][2], bL[2][2];
#pragma unroll
            for (int nf = 0; nf < 2; nf++) {
                int chunk = (wn + (nf << 3)) >> 3;
                int boff = krow * 128 + ((chunk ^ swk) << 4);
                ldsm_x2t(bH[nf], vh0 + boff);
                ldsm_x2t(bL[nf], vl0 + boff);
            }
#pragma unroll
            for (int mf = 0; mf < 2; mf++)
#pragma unroll
                for (int nf = 0; nf < 2; nf++) {
                    mma16816(acc[mf][nf], aH[mf], bH[nf]);
                    mma16816(acc[mf][nf], aH[mf], bL[nf]);
                    mma16816(acc[mf][nf], aL[mf], bH[nf]);
                }
        }
    }

    const int gr = lane >> 2, gc = (lane & 3) << 1;
#pragma unroll
    for (int mf = 0; mf < 2; mf++) {
        int row0 = q0 + wm + (mf << 4) + gr;
#pragma unroll
        for (int nf = 0; nf < 2; nf++) {
            int col = h * HD + wn + (nf << 3) + gc;
            *(float2*)(X + ((size_t)(b * Ss + row0)) * Dd + col) =
                make_float2(acc[mf][nf][0], acc[mf][nf][1]);
            *(float2*)(X + ((size_t)(b * Ss + row0 + 8)) * Dd + col) =
                make_float2(acc[mf][nf][2], acc[mf][nf][3]);
        }
    }
}

// ---------------- launch ----------------
extern "C" void kernel_launch(void* const* d_in, const int* in_sizes, int n_in,
                              void* d_out, int out_size)
{
    const float* query = (const float*)d_in[0];
    const float* key   = (const float*)d_in[1];
    const float* value = (const float*)d_in[2];
    const int*   mask  = (const int*)d_in[3];
    const float* Wq = (const float*)d_in[4];  const float* bq = (const float*)d_in[5];
    const float* Wk = (const float*)d_in[6];  const float* bk = (const float*)d_in[7];
    const float* Wv = (const float*)d_in[8];  const float* bv = (const float*)d_in[9];
    const float* Wo = (const float*)d_in[10]; const float* bo = (const float*)d_in[11];

    float* out = (float*)d_out;
    const size_t BSD = (size_t)Bb * Ss * Dd;
    const size_t ATT = (size_t)BHt * Ss * Ss;

    void *pqh, *pql, *pkh, *pkl, *pvh, *pvl, *px;
    cudaGetSymbolAddress(&pqh, g_qh);
    cudaGetSymbolAddress(&pql, g_ql);
    cudaGetSymbolAddress(&pkh, g_kh);
    cudaGetSymbolAddress(&pkl, g_kl);
    cudaGetSymbolAddress(&pvh, g_vh);
    cudaGetSymbolAddress(&pvl, g_vl);
    cudaGetSymbolAddress(&px, g_x);
    __nv_bfloat16* qh = (__nv_bfloat16*)pqh;
    __nv_bfloat16* ql = (__nv_bfloat16*)pql;
    __nv_bfloat16* kh = (__nv_bfloat16*)pkh;
    __nv_bfloat16* kl = (__nv_bfloat16*)pkl;
    __nv_bfloat16* vh = (__nv_bfloat16*)pvh;
    __nv_bfloat16* vl = (__nv_bfloat16*)pvl;
    float* x = (float*)px;

    float* P;
    if ((size_t)out_size >= BSD + ATT) {
        P = out + BSD;
    } else {
        void* pp;
        cudaGetSymbolAddress(&pp, g_p_fallback);
        P = (float*)pp;
    }

    dim3 gemm_grid(Dd / 128, Mrows / 128);  // (8, 32)

    gemm_f32_tc<<<gemm_grid, 256>>>(query, Wq, bq, nullptr, qh, ql, 1, Mrows, Dd, Dd);
    gemm_f32_tc<<<gemm_grid, 256>>>(key,   Wk, bk, nullptr, kh, kl, 1, Mrows, Dd, Dd);
    gemm_f32_tc<<<gemm_grid, 256>>>(value, Wv, bv, nullptr, vh, vl, 1, Mrows, Dd, Dd);

    attn_energy_tc<<<dim3(Ss / 64, BHt), 256>>>(qh, ql, kh, kl, mask, P);
    attn_pv_tc<<<dim3(Ss / 64, BHt), 256>>>(P, vh, vl, x);

    gemm_f32_tc<<<gemm_grid, 256>>>(x, Wo, bo, out, nullptr, nullptr, 0, Mrows, Dd, Dd);
}